// round 1
// baseline (speedup 1.0000x reference)
#include <cuda_runtime.h>
#include <cstdint>

#define BSZ 256   // batch
#define SS  512   // seq
#define II  128   // in features
#define OO  128   // out features
#define LLG 11    // lags (MAX_LAG+1)
#define HH  16    // modulator hidden
#define BPC 32    // batches per block
#define BCH 8     // batch chunks (BPC*BCH == BSZ)

__device__ float g_xm[BSZ * II];   // mean over S, [b][i]

__device__ __forceinline__ float tanh_fast(float x) {
    float y;
    asm("tanh.approx.f32 %0, %1;" : "=f"(y) : "f"(x));
    return y;
}

__device__ __forceinline__ float sigmoid_p(float x) {
    return __fdividef(1.0f, 1.0f + __expf(-x));
}

// ---------------------------------------------------------------------------
// Kernel 1: xm[b][i] = mean_s x[b][s][i].  One block per b, 512 threads
// (4 s-chunks x 128 i), coalesced, HBM-bound.
// ---------------------------------------------------------------------------
__global__ __launch_bounds__(512) void xm_kernel(const float* __restrict__ x) {
    int b = blockIdx.x;
    int i = threadIdx.x & 127;
    int c = threadIdx.x >> 7;   // 0..3
    const float* p = x + (size_t)b * SS * II + (size_t)c * 128 * II + i;
    float s = 0.0f;
#pragma unroll 8
    for (int j = 0; j < 128; j++) s += p[(size_t)j * II];
    __shared__ float red[4][128];
    red[c][i] = s;
    __syncthreads();
    if (c == 0)
        g_xm[b * II + i] = (red[0][i] + red[1][i] + red[2][i] + red[3][i]) * (1.0f / SS);
}

// ---------------------------------------------------------------------------
// Kernel 2: main.  Thread <-> (o,i) pair; all per-(o,i) params live in
// registers (softmax of lag_logits computed in prologue); loop over a chunk
// of 32 b values with 1-deep software prefetch of hist/xm; block-level
// reduction over i (128 lanes -> 1) per (b,o).
//   grid = (OO/2, BCH), block = 256 threads = 2 o-rows x 128 i.
// ---------------------------------------------------------------------------
__global__ __launch_bounds__(256, 2) void main_kernel(
    const float* __restrict__ x,
    const float* __restrict__ coeffs,
    const float* __restrict__ lag_logits,
    const float* __restrict__ mw1,
    const float* __restrict__ mb1,
    const float* __restrict__ mw2,
    const float* __restrict__ mb2,
    const float* __restrict__ edge,
    float* __restrict__ out)
{
    int tid = threadIdx.x;
    int i  = tid & 127;
    int ol = tid >> 7;                 // 0 or 1
    int o  = blockIdx.x * 2 + ol;
    int oi = o * II + i;
    int b0 = blockIdx.y * BPC;

    // --- softmax over lag logits (once per thread, amortized over BPC) ---
    float wl[LLG];
    float m = -1e30f;
#pragma unroll
    for (int l = 0; l < LLG; l++) { wl[l] = lag_logits[oi * LLG + l]; m = fmaxf(m, wl[l]); }
    float sum = 0.0f;
#pragma unroll
    for (int l = 0; l < LLG; l++) { wl[l] = __expf(wl[l] - m); sum += wl[l]; }
    float inv = __fdividef(1.0f, sum);
#pragma unroll
    for (int l = 0; l < LLG; l++) wl[l] *= inv;

    // --- edge mask folded into coefficients; idx<4 => only coeffs[0..4] ---
    float mask = (edge[oi] > 0.0f) ? 1.0f : 0.0f;
    float C[5];
#pragma unroll
    for (int j = 0; j < 5; j++) C[j] = coeffs[oi * 8 + j] * mask;

    float W1[HH], B1[HH], W2[HH];
#pragma unroll
    for (int h = 0; h < HH; h++) {
        W1[h] = mw1[oi * HH + h];
        B1[h] = mb1[oi * HH + h];
        W2[h] = mw2[oi * HH + h];
    }
    float b2v = mb2[oi];

    __shared__ float red[2][8];

    // hist pointer: x[b0, S-1, i]; lag l is at -l*II
    const float* xb = x + ((size_t)b0 * SS + (SS - 1)) * II + i;
    float hv[LLG], xmv;
#pragma unroll
    for (int l = 0; l < LLG; l++) hv[l] = xb[-(l * II)];
    xmv = g_xm[b0 * II + i];

    for (int bb = 0; bb < BPC; bb++) {
        int b = b0 + bb;

        // prefetch next b
        float hn[LLG], xmn = 0.0f;
#pragma unroll
        for (int l = 0; l < LLG; l++) hn[l] = 0.0f;
        if (bb + 1 < BPC) {
            const float* nb = xb + (size_t)(bb + 1) * SS * II;
#pragma unroll
            for (int l = 0; l < LLG; l++) hn[l] = nb[-(l * II)];
            xmn = g_xm[(b + 1) * II + i];
        }

        // lagged input: sum_l x[b, S-1-l, i] * w_lag[l]
        float xl = 0.0f;
#pragma unroll
        for (int l = 0; l < LLG; l++) xl = fmaf(hv[l], wl[l], xl);

        // spline lookup + lerp
        float s   = sigmoid_p(xl);
        float idx = s * 4.0f;
        int   k   = (int)idx;
        k = (k > 3) ? 3 : k;
        float w1f = idx - (float)k;
        float c0 = (k == 0) ? C[0] : (k == 1) ? C[1] : (k == 2) ? C[2] : C[3];
        float c1 = (k == 0) ? C[1] : (k == 1) ? C[2] : (k == 2) ? C[3] : C[4];
        float y  = fmaf(c1 - c0, w1f, c0);

        // modulator MLP (MUFU.TANH)
        float acc = b2v;
#pragma unroll
        for (int h = 0; h < HH; h++)
            acc = fmaf(tanh_fast(fmaf(xmv, W1[h], B1[h])), W2[h], acc);
        float alpha = sigmoid_p(acc);

        float v = y * alpha;

        // reduce over 128 i lanes (4 warps per o-row)
#pragma unroll
        for (int off = 16; off; off >>= 1)
            v += __shfl_xor_sync(0xffffffffu, v, off);
        if ((tid & 31) == 0) red[bb & 1][tid >> 5] = v;
        __syncthreads();
        if (tid < 2) {
            const float* r = red[bb & 1] + tid * 4;
            out[(size_t)b * OO + blockIdx.x * 2 + tid] = r[0] + r[1] + r[2] + r[3];
        }

#pragma unroll
        for (int l = 0; l < LLG; l++) hv[l] = hn[l];
        xmv = xmn;
    }
}

extern "C" void kernel_launch(void* const* d_in, const int* in_sizes, int n_in,
                              void* d_out, int out_size) {
    const float* x      = (const float*)d_in[0];
    const float* coeffs = (const float*)d_in[1];
    const float* lag    = (const float*)d_in[2];
    const float* mw1    = (const float*)d_in[3];
    const float* mb1    = (const float*)d_in[4];
    const float* mw2    = (const float*)d_in[5];
    const float* mb2    = (const float*)d_in[6];
    const float* edge   = (const float*)d_in[7];
    float* out = (float*)d_out;

    xm_kernel<<<BSZ, 512>>>(x);
    dim3 grid(OO / 2, BCH);
    main_kernel<<<grid, 256>>>(x, coeffs, lag, mw1, mb1, mw2, mb2, edge, out);
}

// round 2
// speedup vs baseline: 1.2398x; 1.2398x over previous
#include <cuda_runtime.h>
#include <cstdint>

#define BSZ 256   // batch
#define SS  512   // seq
#define II  128   // in features
#define OO  128   // out features
#define LLG 11    // lags (MAX_LAG+1)
#define HH  16    // modulator hidden
#define BPC 32    // batches per block chunk
#define BCH 8     // batch chunks (BPC*BCH == BSZ)
#define UF  4     // batches processed per inner iteration

__device__ float g_xm[BSZ * II];   // mean over S, [b][i]

__device__ __forceinline__ float tanh_fast(float x) {
    float y;
    asm("tanh.approx.f32 %0, %1;" : "=f"(y) : "f"(x));
    return y;
}

// sigmoid(x) = 0.5*tanh(x/2) + 0.5   (single MUFU)
__device__ __forceinline__ float sigmoid_t(float x) {
    return fmaf(tanh_fast(0.5f * x), 0.5f, 0.5f);
}

// ---------------------------------------------------------------------------
// Kernel 1: xm[b][i] = mean_s x[b][s][i]; also zeroes out[b][:] so the main
// kernel can accumulate with RED.E.ADD.  One block per b, 512 threads.
// ---------------------------------------------------------------------------
__global__ __launch_bounds__(512) void xm_kernel(const float* __restrict__ x,
                                                 float* __restrict__ out) {
    int b = blockIdx.x;
    int i = threadIdx.x & 127;
    int c = threadIdx.x >> 7;   // 0..3
    if (threadIdx.x < OO) out[(size_t)b * OO + threadIdx.x] = 0.0f;
    const float* p = x + (size_t)b * SS * II + (size_t)c * 128 * II + i;
    float s = 0.0f;
#pragma unroll 8
    for (int j = 0; j < 128; j++) s += p[(size_t)j * II];
    __shared__ float red[4][128];
    red[c][i] = s;
    __syncthreads();
    if (c == 0)
        g_xm[b * II + i] = (red[0][i] + red[1][i] + red[2][i] + red[3][i]) * (1.0f / SS);
}

// ---------------------------------------------------------------------------
// Kernel 2: main.  Thread <-> (o,i); per-(o,i) params in registers; UF=4
// batches per iteration for ILP; warp shfl reduce (4 interleaved) + one
// RED.E.ADD per (b,o) partial.  No shared memory, no __syncthreads.
//   grid = (OO/2, BCH), block = 256 threads = 2 o-rows x 128 i.
// ---------------------------------------------------------------------------
__global__ __launch_bounds__(256, 2) void main_kernel(
    const float* __restrict__ x,
    const float* __restrict__ coeffs,
    const float* __restrict__ lag_logits,
    const float* __restrict__ mw1,
    const float* __restrict__ mb1,
    const float* __restrict__ mw2,
    const float* __restrict__ mb2,
    const float* __restrict__ edge,
    float* __restrict__ out)
{
    int tid = threadIdx.x;
    int i  = tid & 127;
    int ol = tid >> 7;                 // 0 or 1
    int o  = blockIdx.x * 2 + ol;
    int oi = o * II + i;
    int b0 = blockIdx.y * BPC;

    // --- softmax over lag logits (amortized over BPC batches) ---
    float wl[LLG];
    float m = -1e30f;
#pragma unroll
    for (int l = 0; l < LLG; l++) { wl[l] = lag_logits[oi * LLG + l]; m = fmaxf(m, wl[l]); }
    float sum = 0.0f;
#pragma unroll
    for (int l = 0; l < LLG; l++) { wl[l] = __expf(wl[l] - m); sum += wl[l]; }
    float inv = __fdividef(1.0f, sum);
#pragma unroll
    for (int l = 0; l < LLG; l++) wl[l] *= inv;

    // --- edge mask folded into coefficients; s*4 < 4 => only coeffs[0..4] ---
    float mask = (edge[oi] > 0.0f) ? 1.0f : 0.0f;
    float C[5];
#pragma unroll
    for (int j = 0; j < 5; j++) C[j] = coeffs[oi * 8 + j] * mask;

    float W1[HH], B1[HH], W2[HH];
#pragma unroll
    for (int h = 0; h < HH; h++) {
        W1[h] = mw1[oi * HH + h];
        B1[h] = mb1[oi * HH + h];
        W2[h] = mw2[oi * HH + h];
    }
    float b2v = mb2[oi];

    // hist pointer: x[b0, S-1, i]; lag l is at -l*II
    const float* xb = x + ((size_t)b0 * SS + (SS - 1)) * II + i;
    const float* xmp = g_xm + (size_t)b0 * II + i;
    float* outp = out + (size_t)b0 * OO + o;

    for (int bb = 0; bb < BPC; bb += UF) {
        float v[UF];
#pragma unroll
        for (int u = 0; u < UF; u++) {
            const float* hp = xb + (size_t)(bb + u) * SS * II;
            float xmv = xmp[(bb + u) * II];

            // lagged input: sum_l x[b, S-1-l, i] * w_lag[l]
            float xl = 0.0f;
#pragma unroll
            for (int l = 0; l < LLG; l++) xl = fmaf(hp[-(l * II)], wl[l], xl);

            // spline lookup + lerp
            float s   = sigmoid_t(xl);
            float idx = s * 4.0f;
            int   k   = (int)idx;
            k = (k > 3) ? 3 : k;
            float w1f = idx - (float)k;
            float c0 = (k == 0) ? C[0] : (k == 1) ? C[1] : (k == 2) ? C[2] : C[3];
            float c1 = (k == 0) ? C[1] : (k == 1) ? C[2] : (k == 2) ? C[3] : C[4];
            float y  = fmaf(c1 - c0, w1f, c0);

            // modulator MLP (MUFU.TANH)
            float acc = b2v;
#pragma unroll
            for (int h = 0; h < HH; h++)
                acc = fmaf(tanh_fast(fmaf(xmv, W1[h], B1[h])), W2[h], acc);
            float alpha = sigmoid_t(acc);

            v[u] = y * alpha;
        }

        // warp-level i-reduction, 4 independent trees interleaved
#pragma unroll
        for (int off = 16; off; off >>= 1)
#pragma unroll
            for (int u = 0; u < UF; u++)
                v[u] += __shfl_xor_sync(0xffffffffu, v[u], off);

        if ((tid & 31) == 0) {
#pragma unroll
            for (int u = 0; u < UF; u++)
                atomicAdd(outp + (size_t)(bb + u) * OO, v[u]);  // -> RED.E.ADD
        }
    }
}

extern "C" void kernel_launch(void* const* d_in, const int* in_sizes, int n_in,
                              void* d_out, int out_size) {
    const float* x      = (const float*)d_in[0];
    const float* coeffs = (const float*)d_in[1];
    const float* lag    = (const float*)d_in[2];
    const float* mw1    = (const float*)d_in[3];
    const float* mb1    = (const float*)d_in[4];
    const float* mw2    = (const float*)d_in[5];
    const float* mb2    = (const float*)d_in[6];
    const float* edge   = (const float*)d_in[7];
    float* out = (float*)d_out;

    xm_kernel<<<BSZ, 512>>>(x, out);
    dim3 grid(OO / 2, BCH);
    main_kernel<<<grid, 256>>>(x, coeffs, lag, mw1, mb1, mw2, mb2, edge, out);
}